// round 14
// baseline (speedup 1.0000x reference)
#include <cuda_runtime.h>
#include <cuda_bf16.h>
#include <cstdint>
#include <math.h>

#define BATCH 4
#define CCH 128
#define NPIX (BATCH*256*256)     /* 262144 */

// ---------------- device scratch ----------------
__device__ float g_bc[CCH];
// bf16 weight bank: [0..2]=qkv, [3]=Wc, [4]=out_w, [5]=tok_w, [6]=lpw,
// [7..10]=fc1 chunks, [11..14]=fc2 chunks. Each 128x128 row-major.
__device__ __nv_bfloat16 g_wbf[15*16384];
__device__ float g_x1[NPIX*CCH];          // x + merged attn, channels-last fp32
__device__ __nv_bfloat16 g_z[NPIX*CCH];   // lpw out, channels-last bf16

// ---------------- helpers ----------------
__device__ __forceinline__ uint32_t bf2(float a, float b) {
    __nv_bfloat162 t = __floats2bfloat162_rn(a, b);
    return *reinterpret_cast<uint32_t*>(&t);
}
__device__ __forceinline__ float2 ubf2f(uint32_t w) {
    __nv_bfloat162 t = *reinterpret_cast<__nv_bfloat162*>(&w);
    return make_float2(__bfloat162float(t.x), __bfloat162float(t.y));
}

// exact-GELU via FMA-only erf polynomial (|z|<=1); rare tail uses erff
__device__ __forceinline__ float gelu_f(float v) {
    float z = v * 0.7071067811865475f;
    float e;
    if (fabsf(z) <= 1.0f) {
        float s = z*z;
        e = 7.853861595399774e-5f;
        e = e*s - 8.010193625184903e-4f;
        e = e*s + 5.188327685732524e-3f;
        e = e*s - 2.685381193529856e-2f;
        e = e*s + 1.128358514861418e-1f;
        e = e*s - 3.761262582423300e-1f;
        e = e*s + 1.128379165726710f;
        e = e*z;
    } else {
        e = erff(z);
    }
    return v * (0.5f + 0.5f*e);
}

__device__ __forceinline__ void mma16(float* c, const uint32_t* a, const uint32_t* b) {
    asm volatile(
        "mma.sync.aligned.m16n8k16.row.col.f32.bf16.bf16.f32 "
        "{%0,%1,%2,%3},{%4,%5,%6,%7},{%8,%9},{%0,%1,%2,%3};"
        : "+f"(c[0]), "+f"(c[1]), "+f"(c[2]), "+f"(c[3])
        : "r"(a[0]), "r"(a[1]), "r"(a[2]), "r"(a[3]), "r"(b[0]), "r"(b[1]));
}

#define LDSM4(R, addr) \
    asm volatile("ldmatrix.sync.aligned.m8n8.x4.shared.b16 {%0,%1,%2,%3}, [%4];" \
        : "=r"(R[0]), "=r"(R[1]), "=r"(R[2]), "=r"(R[3]) : "r"(addr))

// async stage: prepacked 128x128 bf16 weight -> smem [128][136]
__device__ __forceinline__ void stage_async(const __nv_bfloat16* __restrict__ Wb,
                                            __nv_bfloat16* __restrict__ sW, int tid) {
    uint32_t s = (uint32_t)__cvta_generic_to_shared(sW);
    const char* gp = (const char*)Wb;
    #pragma unroll
    for (int i = tid; i < 2048; i += 512) {
        int row = i >> 4, c8 = (i & 15) << 3;
        asm volatile("cp.async.cg.shared.global [%0], [%1], 16;"
            :: "r"(s + (uint32_t)(row*136 + c8)*2), "l"(gp + i*16));
    }
    asm volatile("cp.async.commit_group;" ::: "memory");
}
__device__ __forceinline__ void stage_wait0() {
    asm volatile("cp.async.wait_group 0;" ::: "memory");
}

// 64x128 GEMM tile, K=128, bf16 in, fp32 accum. 16 warps, warp tile 16x32.
__device__ __forceinline__ void mma_gemm64(const __nv_bfloat16* __restrict__ sA, int strideA,
                                           const __nv_bfloat16* __restrict__ sW,
                                           float acc[4][4], int warp, int lane) {
    int quad = lane >> 3, r = lane & 7;
    uint32_t aAddr = (uint32_t)__cvta_generic_to_shared(sA)
        + (uint32_t)((((warp & 3)*16 + (quad & 1)*8 + r) * strideA + (quad >> 1)*8) * 2);
    uint32_t bAddr = (uint32_t)__cvta_generic_to_shared(sW)
        + (uint32_t)((((warp >> 2)*32 + (quad >> 1)*8 + r) * 136 + (quad & 1)*8) * 2);
    const uint32_t bStep = 16 * 136 * 2;
    #pragma unroll
    for (int kt = 0; kt < 8; ++kt) {
        uint32_t A0[4], B0[4], B1[4];
        LDSM4(A0, aAddr);
        LDSM4(B0, bAddr);
        LDSM4(B1, bAddr + bStep);
        aAddr += 32; bAddr += 32;
        mma16(acc[0], A0, B0);     mma16(acc[1], A0, B0 + 2);
        mma16(acc[2], A0, B1);     mma16(acc[3], A0, B1 + 2);
    }
}

// 128x128 version for leff (16 warps, 32x32 each)
__device__ __forceinline__ void mma_gemm16(const __nv_bfloat16* __restrict__ sA, int strideA,
                                           const __nv_bfloat16* __restrict__ sW,
                                           float acc[2][4][4], int warp, int lane) {
    int quad = lane >> 3, r = lane & 7;
    uint32_t aAddr = (uint32_t)__cvta_generic_to_shared(sA)
        + (uint32_t)((((warp & 3)*32 + (quad & 1)*8 + r) * strideA + (quad >> 1)*8) * 2);
    uint32_t bAddr = (uint32_t)__cvta_generic_to_shared(sW)
        + (uint32_t)((((warp >> 2)*32 + (quad >> 1)*8 + r) * 136 + (quad & 1)*8) * 2);
    uint32_t aStep = (uint32_t)(16 * strideA * 2);
    const uint32_t bStep = 16 * 136 * 2;
    #pragma unroll
    for (int kt = 0; kt < 8; ++kt) {
        uint32_t A0[4], A1[4], B0[4], B1[4];
        LDSM4(A0, aAddr);
        LDSM4(A1, aAddr + aStep);
        LDSM4(B0, bAddr);
        LDSM4(B1, bAddr + bStep);
        aAddr += 32; bAddr += 32;
        mma16(acc[0][0], A0, B0);     mma16(acc[0][1], A0, B0 + 2);
        mma16(acc[0][2], A0, B1);     mma16(acc[0][3], A0, B1 + 2);
        mma16(acc[1][0], A1, B0);     mma16(acc[1][1], A1, B0 + 2);
        mma16(acc[1][2], A1, B1);     mma16(acc[1][3], A1, B1 + 2);
    }
}

// Half-N variant for leff fc1 (tacc = 16 regs, no spills)
__device__ __forceinline__ void mma_gemm16_n2(const __nv_bfloat16* __restrict__ sA, int strideA,
                                              const __nv_bfloat16* __restrict__ sW,
                                              float acc[2][2][4], int warp, int lane, int nhalf) {
    int quad = lane >> 3, r = lane & 7;
    uint32_t aAddr = (uint32_t)__cvta_generic_to_shared(sA)
        + (uint32_t)((((warp & 3)*32 + (quad & 1)*8 + r) * strideA + (quad >> 1)*8) * 2);
    uint32_t bAddr = (uint32_t)__cvta_generic_to_shared(sW)
        + (uint32_t)((((warp >> 2)*32 + nhalf*16 + (quad >> 1)*8 + r) * 136 + (quad & 1)*8) * 2);
    uint32_t aStep = (uint32_t)(16 * strideA * 2);
    #pragma unroll
    for (int kt = 0; kt < 8; ++kt) {
        uint32_t A0[4], A1[4], B0[4];
        LDSM4(A0, aAddr);
        LDSM4(A1, aAddr + aStep);
        LDSM4(B0, bAddr);
        aAddr += 32; bAddr += 32;
        mma16(acc[0][0], A0, B0);     mma16(acc[0][1], A0, B0 + 2);
        mma16(acc[1][0], A1, B0);     mma16(acc[1][1], A1, B0 + 2);
    }
}

// ---------------- K0: pack weights to bf16 bank (Wc fused inline) ----------------
__global__ void k_prep(const float* __restrict__ qkv_w, const float* __restrict__ out_w,
                       const float* __restrict__ tok_w, const float* __restrict__ lpw_w,
                       const float* __restrict__ fc1_w, const float* __restrict__ fc2_w,
                       const float* __restrict__ convp_w, const float* __restrict__ convp_b,
                       const float* __restrict__ pw1_w,   const float* __restrict__ pw1_b) {
    int idx = blockIdx.x*256 + threadIdx.x;
    int blk = idx >> 14;
    int m = idx & 16383;
    int c = m >> 7, k = m & 127;
    float v;
    if      (blk < 3)  v = qkv_w[blk*16384 + m];
    else if (blk == 3) {
        v = 0.f;
        for (int i = 0; i < CCH; ++i) v += pw1_w[c*CCH + i] * convp_w[i*CCH + k];
    }
    else if (blk == 4) v = out_w[m];
    else if (blk == 5) v = tok_w[m];
    else if (blk == 6) v = lpw_w[m];
    else if (blk < 11) v = fc1_w[(blk-7)*16384 + m];
    else               v = fc2_w[c*512 + (blk-11)*128 + k];
    g_wbf[idx] = __float2bfloat16(v);
    if (idx < CCH) {
        float b = pw1_b[idx];
        for (int i = 0; i < CCH; ++i) b += pw1_w[idx*CCH + i] * convp_b[i];
        g_bc[idx] = b;
    }
}

// ---------------- ReMSA + LN1 + LN2 + lpw fused: 1 window/CTA, 512 thr, 2 CTAs/SM ----------------
__global__ void __launch_bounds__(512, 2)
k_remsa(const float* __restrict__ x,
        const float* __restrict__ n1w, const float* __restrict__ n1b,
        const float* __restrict__ qkv_b, const float* __restrict__ pos_bias,
        const float* __restrict__ out_b, const float* __restrict__ tok_b,
        const float* __restrict__ dw1_w, const float* __restrict__ dw1_b,
        const float* __restrict__ n2w, const float* __restrict__ n2b) {
    extern __shared__ __align__(16) char smem[];
    __nv_bfloat16* s_qkv = (__nv_bfloat16*)smem;                   // 64 x 392 bf16 (also fp32 tile)
    __nv_bfloat16* s_y   = (__nv_bfloat16*)(smem + 50176);         // 64 x 136 (LN1 / xc / LN2)
    __nv_bfloat16* s_W   = (__nv_bfloat16*)(smem + 50176 + 17408); // 128 x 136
    __shared__ float s_mu[64], s_rs[64];
    int tid = threadIdx.x, warp = tid >> 5, lane = tid & 31;
    int win = blockIdx.x;
    int bb  = win >> 10;
    int h0  = ((win >> 5) & 31) * 8;
    int w0  = (win & 31) * 8;

    stage_async(g_wbf, s_W, tid);    // prefetch qkv chunk 0

    // ---- LN1: load x tile (128 ch x 8 rows x 8 cols) into s_x fp32 ----
    float* s_x = (float*)s_qkv;      // [64 tokens][129]
    const float* xb = x + (size_t)bb*CCH*65536 + h0*256 + w0;
    #pragma unroll
    for (int it = 0; it < 4; ++it) {
        int idx = tid + it*512;                 // 2048 float4
        int c = idx >> 4, r = (idx >> 1) & 7, w4 = idx & 1;
        float4 v = *(const float4*)(xb + c*65536 + r*256 + w4*4);
        int row0 = r*8 + w4*4;
        s_x[(row0  )*129 + c] = v.x;
        s_x[(row0+1)*129 + c] = v.y;
        s_x[(row0+2)*129 + c] = v.z;
        s_x[(row0+3)*129 + c] = v.w;
    }
    __syncthreads();
    {
        int p = tid >> 3, q = tid & 7;
        float sm = 0.f, sq = 0.f;
        #pragma unroll
        for (int i = 0; i < 16; ++i) { float v = s_x[p*129 + q*16 + i]; sm += v; sq += v*v; }
        sm += __shfl_xor_sync(0xffffffffu, sm, 1); sq += __shfl_xor_sync(0xffffffffu, sq, 1);
        sm += __shfl_xor_sync(0xffffffffu, sm, 2); sq += __shfl_xor_sync(0xffffffffu, sq, 2);
        sm += __shfl_xor_sync(0xffffffffu, sm, 4); sq += __shfl_xor_sync(0xffffffffu, sq, 4);
        if (q == 0) {
            float mu = sm * (1.f/128.f);
            float var = sq * (1.f/128.f) - mu*mu;
            s_mu[p] = mu; s_rs[p] = rsqrtf(var + 1e-5f);
        }
    }
    __syncthreads();
    uint32_t* s_yw = (uint32_t*)s_y;
    for (int idx = tid; idx < 4096; idx += 512) {
        int pp = idx >> 6, cw = idx & 63, c0 = cw*2;
        float mu = s_mu[pp], rs = s_rs[pp];
        float v0 = (s_x[pp*129 + c0]   - mu) * rs * n1w[c0]   + n1b[c0];
        float v1 = (s_x[pp*129 + c0+1] - mu) * rs * n1w[c0+1] + n1b[c0+1];
        s_yw[pp*68 + cw] = bf2(v0, v1);
    }

    int g = lane >> 2, tg = lane & 3;
    int rbase = (warp & 3) * 16 + g;
    int cbase = (warp >> 2) * 32;
    uint32_t* qw = (uint32_t*)s_qkv;   // stride 196 words per row (overwrites s_x)

    // Phase A (chunks 0..2): qkv GEMMs (64 x 384) -> s_qkv, REMAPPED to block [Q|K|V] layout.
    // Global channel cg = chunk*128 + c -> (head=cg/48, type=(cg%48)/16, d=cg%16)
    // dest word = type*64 + head*8 + d/2   (even channel pairs never straddle a type boundary)
    for (int chunk = 0; chunk < 3; ++chunk) {
        stage_wait0();
        __syncthreads();
        float acc[4][4] = {};
        mma_gemm64(s_y, 136, s_W, acc, warp, lane);
        __syncthreads();
        stage_async(g_wbf + (chunk+1)*16384, s_W, tid);   // qkv1, qkv2, then Wc
        const float* bsrc = qkv_b + chunk*128;
        #pragma unroll
        for (int nt = 0; nt < 4; ++nt) {
            int c0 = cbase + nt*8 + 2*tg;
            float b0 = bsrc[c0], b1 = bsrc[c0+1];
            int cg = chunk*128 + c0;
            int head = cg / 48, rem = cg % 48;
            int off = (rem >> 4)*64 + head*8 + ((rem & 15) >> 1);
            qw[ rbase   *196 + off] = bf2(acc[nt][0] + b0, acc[nt][1] + b1);
            qw[(rbase+8)*196 + off] = bf2(acc[nt][2] + b0, acc[nt][3] + b1);
        }
    }
    __syncthreads();

    // Phase B: head-mixing attention; 8 threads/token, 1 head each; ao overwrites q in place
    {
        int n = tid >> 3, hI = tid & 7;
        uint32_t* base = qw + n*196;
        const float* pb = pos_bias + n*64 + hI*8;
        float qv[16];
        #pragma unroll
        for (int d = 0; d < 8; ++d) {
            float2 f = ubf2f(base[hI*8 + d]);
            qv[2*d] = f.x; qv[2*d+1] = f.y;
        }
        float sc[8]; float mx = -1e30f;
        #pragma unroll
        for (int gg = 0; gg < 8; ++gg) {
            const uint32_t* kp = base + 64 + gg*8;
            float sd = 0.f;
            #pragma unroll
            for (int d = 0; d < 8; ++d) {
                float2 f = ubf2f(kp[d]);
                sd += qv[2*d]*f.x + qv[2*d+1]*f.y;
            }
            sc[gg] = sd*0.25f + pb[gg];
            mx = fmaxf(mx, sc[gg]);
        }
        float ssum = 0.f;
        #pragma unroll
        for (int gg = 0; gg < 8; ++gg) { sc[gg] = __expf(sc[gg] - mx); ssum += sc[gg]; }
        float inv = 1.f / ssum;
        float ao[16];
        #pragma unroll
        for (int d = 0; d < 16; ++d) ao[d] = 0.f;
        #pragma unroll
        for (int gg = 0; gg < 8; ++gg) {
            float a = sc[gg]*inv;
            const uint32_t* vp = base + 128 + gg*8;
            #pragma unroll
            for (int d = 0; d < 8; ++d) {
                float2 f = ubf2f(vp[d]);
                ao[2*d]   += a*f.x;
                ao[2*d+1] += a*f.y;
            }
        }
        #pragma unroll
        for (int d = 0; d < 8; ++d)
            base[hI*8 + d] = bf2(ao[2*d], ao[2*d+1]);   // own head's q slot
    }

    // Phase A': chunk 3 (Wc) GEMM reading s_y; result held in regs, then xc -> s_y
    stage_wait0();
    __syncthreads();
    {
        float acc[4][4] = {};
        mma_gemm64(s_y, 136, s_W, acc, warp, lane);
        __syncthreads();                              // everyone done reading s_y
        stage_async(g_wbf + 4*16384, s_W, tid);       // out_w
        #pragma unroll
        for (int nt = 0; nt < 4; ++nt) {
            int c0 = cbase + nt*8 + 2*tg;
            float b0 = g_bc[c0], b1 = g_bc[c0+1];
            s_yw[ rbase   *68 + (c0 >> 1)] = bf2(acc[nt][0] + b0, acc[nt][1] + b1);
            s_yw[(rbase+8)*68 + (c0 >> 1)] = bf2(acc[nt][2] + b0, acc[nt][3] + b1);
        }
    }
    __syncthreads();

    // Phase C: token-dim dwconv on xc (s_y) -> k region (words 64..127)
    for (int idx = tid; idx < 4096; idx += 512) {
        int n = idx >> 6, cw = idx & 63;
        int c0 = cw*2;
        float2 m  = ubf2f(s_yw[n*68 + cw]);
        float2 lo = make_float2(0.f, 0.f), hi = make_float2(0.f, 0.f);
        if (n > 0)  lo = ubf2f(s_yw[(n-1)*68 + cw]);
        if (n < 63) hi = ubf2f(s_yw[(n+1)*68 + cw]);
        float d0 = lo.x*dw1_w[c0*3]   + m.x*dw1_w[c0*3+1] + hi.x*dw1_w[c0*3+2] + dw1_b[c0];
        float d1 = lo.y*dw1_w[c0*3+3] + m.y*dw1_w[c0*3+4] + hi.y*dw1_w[c0*3+5] + dw1_b[c0+1];
        qw[n*196 + 64 + cw] = bf2(d0, d1);
    }
    stage_wait0();
    __syncthreads();

    // Phase D: ao @ out_w^T + dconv @ tok_w^T
    float acc[4][4] = {};
    mma_gemm64(s_qkv, 392, s_W, acc, warp, lane);          // ao (bf16 cols 0..127)
    __syncthreads();
    stage_async(g_wbf + 5*16384, s_W, tid);                // tok_w
    stage_wait0();
    __syncthreads();
    mma_gemm64(s_qkv + 128, 392, s_W, acc, warp, lane);    // dconv (bf16 cols 128..255)
    __syncthreads();                                       // all s_qkv reads done
    stage_async(g_wbf + 6*16384, s_W, tid);                // lpw
    float* s_att = (float*)s_qkv;                          // [64][129] fp32
    #pragma unroll
    for (int nt = 0; nt < 4; ++nt) {
        int c0 = cbase + nt*8 + 2*tg;
        float b0 = out_b[c0] + tok_b[c0], b1 = out_b[c0+1] + tok_b[c0+1];
        s_att[ rbase   *129 + c0]     = acc[nt][0] + b0;
        s_att[ rbase   *129 + c0 + 1] = acc[nt][1] + b1;
        s_att[(rbase+8)*129 + c0]     = acc[nt][2] + b0;
        s_att[(rbase+8)*129 + c0 + 1] = acc[nt][3] + b1;
    }
    __syncthreads();

    // Phase E (fused LN2): x1 = x + att; write g_x1; LN -> bf16 s_y
    {
        int p = tid >> 3, q = tid & 7;
        int hh = h0 + (p >> 3), ww = w0 + (p & 7);
        const float* xp = x + (size_t)bb*CCH*65536 + hh*256 + ww + (size_t)q*16*65536;
        float x1[16];
        #pragma unroll
        for (int i = 0; i < 16; ++i)
            x1[i] = xp[(size_t)i*65536] + s_att[p*129 + q*16 + i];
        float* xo = g_x1 + ((size_t)(bb*65536 + hh*256 + ww))*128 + q*16;
        #pragma unroll
        for (int i = 0; i < 4; ++i)
            *(float4*)(xo + i*4) = make_float4(x1[4*i], x1[4*i+1], x1[4*i+2], x1[4*i+3]);
        float sm = 0.f, sq = 0.f;
        #pragma unroll
        for (int i = 0; i < 16; ++i) { sm += x1[i]; sq += x1[i]*x1[i]; }
        sm += __shfl_xor_sync(0xffffffffu, sm, 1); sq += __shfl_xor_sync(0xffffffffu, sq, 1);
        sm += __shfl_xor_sync(0xffffffffu, sm, 2); sq += __shfl_xor_sync(0xffffffffu, sq, 2);
        sm += __shfl_xor_sync(0xffffffffu, sm, 4); sq += __shfl_xor_sync(0xffffffffu, sq, 4);
        float mu = sm * (1.f/128.f);
        float rs = rsqrtf(sq * (1.f/128.f) - mu*mu + 1e-5f);
        #pragma unroll
        for (int j = 0; j < 8; ++j) {
            int c0 = q*16 + 2*j;
            float v0 = (x1[2*j]   - mu) * rs * n2w[c0]   + n2b[c0];
            float v1 = (x1[2*j+1] - mu) * rs * n2w[c0+1] + n2b[c0+1];
            s_yw[p*68 + q*8 + j] = bf2(v0, v1);
        }
    }
    stage_wait0();
    __syncthreads();

    // Phase F: lpw GEMM -> g_z (bf16 channels-last)
    float zacc[4][4] = {};
    mma_gemm64(s_y, 136, s_W, zacc, warp, lane);
    uint32_t* zw = (uint32_t*)g_z;
    #pragma unroll
    for (int nt = 0; nt < 4; ++nt) {
        int c0 = cbase + nt*8 + 2*tg;
        int n0 = rbase, n1 = rbase + 8;
        size_t pa = (size_t)(bb*65536 + (h0 + (n0 >> 3))*256 + w0 + (n0 & 7));
        size_t pc = (size_t)(bb*65536 + (h0 + (n1 >> 3))*256 + w0 + (n1 & 7));
        zw[pa*64 + (c0 >> 1)] = bf2(zacc[nt][0], zacc[nt][1]);
        zw[pc*64 + (c0 >> 1)] = bf2(zacc[nt][2], zacc[nt][3]);
    }
}

// ---------------- LeFF: 128 pixels per CTA, 512 threads, 2 CTAs/SM ----------------
__global__ void __launch_bounds__(512, 2) k_leff(const float* __restrict__ ldw_w,
                                                 const float* __restrict__ ldw_b,
                                                 const float* __restrict__ fc1_b,
                                                 const float* __restrict__ fc2_b,
                                                 float* __restrict__ out) {
    extern __shared__ __align__(16) char smem[];
    __nv_bfloat16* s_d = (__nv_bfloat16*)smem;                   // 128*136
    __nv_bfloat16* s_t = (__nv_bfloat16*)(smem + 34816);         // 128*136
    __nv_bfloat16* s_W = (__nv_bfloat16*)(smem + 69632);         // 128*136
    float* s_f = (float*)(smem + 34816);                         // aliases s_t + s_W
    int tid = threadIdx.x, warp = tid >> 5, lane = tid & 31, bid = blockIdx.x;
    int w0 = (bid & 1) * 128;
    int h  = (bid >> 1) & 255;
    int bb = bid >> 9;

    stage_async(g_wbf + 7*16384, s_W, tid);    // fc1[0]

    // 3x3 depthwise over g_z (bf16 channels-last), uint4-vectorized
    {
        const uint4* zw4 = (const uint4*)g_z;
        #pragma unroll
        for (int it = 0; it < 4; ++it) {
            int idx = tid + it*512;
            int p = idx >> 4, c16 = idx & 15;
            int c0 = c16*8;
            int xx0 = w0 + p;
            float acc[8];
            #pragma unroll
            for (int j = 0; j < 8; ++j) acc[j] = ldw_b[c0 + j];
            #pragma unroll
            for (int dy = 0; dy < 3; ++dy) {
                int yy = h + dy - 1;
                if (yy < 0 || yy > 255) continue;
                #pragma unroll
                for (int dx = 0; dx < 3; ++dx) {
                    int xx = xx0 + dx - 1;
                    if (xx < 0 || xx > 255) continue;
                    uint4 u = zw4[((size_t)(bb*65536 + yy*256 + xx))*16 + c16];
                    float2 f;
                    f = ubf2f(u.x); acc[0] += f.x*ldw_w[(c0  )*9 + dy*3 + dx];
                                    acc[1] += f.y*ldw_w[(c0+1)*9 + dy*3 + dx];
                    f = ubf2f(u.y); acc[2] += f.x*ldw_w[(c0+2)*9 + dy*3 + dx];
                                    acc[3] += f.y*ldw_w[(c0+3)*9 + dy*3 + dx];
                    f = ubf2f(u.z); acc[4] += f.x*ldw_w[(c0+4)*9 + dy*3 + dx];
                                    acc[5] += f.y*ldw_w[(c0+5)*9 + dy*3 + dx];
                    f = ubf2f(u.w); acc[6] += f.x*ldw_w[(c0+6)*9 + dy*3 + dx];
                                    acc[7] += f.y*ldw_w[(c0+7)*9 + dy*3 + dx];
                }
            }
            uint4 o;
            o.x = bf2(acc[0], acc[1]); o.y = bf2(acc[2], acc[3]);
            o.z = bf2(acc[4], acc[5]); o.w = bf2(acc[6], acc[7]);
            *(uint4*)((uint32_t*)s_d + p*68 + c16*4) = o;
        }
    }

    int g = lane >> 2, tg = lane & 3;
    int rbase = (warp & 3) * 32 + g;
    int cbase = (warp >> 2) * 32;
    float oacc[2][4][4] = {};
    for (int jc = 0; jc < 4; ++jc) {
        stage_wait0();
        __syncthreads();
        uint32_t* tw = (uint32_t*)s_t;
        #pragma unroll
        for (int half = 0; half < 2; ++half) {
            float tacc[2][2][4] = {};
            mma_gemm16_n2(s_d, 136, s_W, tacc, warp, lane, half);
            #pragma unroll
            for (int mt = 0; mt < 2; ++mt)
                #pragma unroll
                for (int nt = 0; nt < 2; ++nt) {
                    int r0 = rbase + mt*16;
                    int c0 = cbase + half*16 + nt*8 + 2*tg;
                    float b0 = fc1_b[jc*128 + c0], b1 = fc1_b[jc*128 + c0 + 1];
                    float v0 = gelu_f(tacc[mt][nt][0] + b0);
                    float v1 = gelu_f(tacc[mt][nt][1] + b1);
                    float v2 = gelu_f(tacc[mt][nt][2] + b0);
                    float v3 = gelu_f(tacc[mt][nt][3] + b1);
                    tw[ r0   *68 + (c0 >> 1)] = bf2(v0, v1);
                    tw[(r0+8)*68 + (c0 >> 1)] = bf2(v2, v3);
                }
        }
        __syncthreads();
        stage_async(g_wbf + (11+jc)*16384, s_W, tid);   // fc2[jc]
        stage_wait0();
        __syncthreads();
        mma_gemm16(s_t, 136, s_W, oacc, warp, lane);
        __syncthreads();
        if (jc < 3) stage_async(g_wbf + (8+jc)*16384, s_W, tid);   // fc1[jc+1]
    }

    // epilogue: + fc2_b + residual x1 (fp32), stage fp32, transpose-write NCHW
    size_t pixb = (size_t)(bb*65536 + h*256 + w0);
    #pragma unroll
    for (int mt = 0; mt < 2; ++mt)
        #pragma unroll
        for (int nt = 0; nt < 4; ++nt) {
            int r0 = rbase + mt*16;
            int c0 = cbase + nt*8 + 2*tg;
            float b0 = fc2_b[c0], b1 = fc2_b[c0+1];
            float2 x0 = *(const float2*)&g_x1[(pixb + r0)  *128 + c0];
            float2 x1 = *(const float2*)&g_x1[(pixb + r0+8)*128 + c0];
            s_f[ r0   *129 + c0]     = oacc[mt][nt][0] + b0 + x0.x;
            s_f[ r0   *129 + c0 + 1] = oacc[mt][nt][1] + b1 + x0.y;
            s_f[(r0+8)*129 + c0]     = oacc[mt][nt][2] + b0 + x1.x;
            s_f[(r0+8)*129 + c0 + 1] = oacc[mt][nt][3] + b1 + x1.y;
        }
    __syncthreads();
    for (int idx = tid; idx < 16384; idx += 512) {
        int c = idx >> 7, p = idx & 127;
        out[((size_t)(bb*128 + c)*256 + h)*256 + w0 + p] = s_f[p*129 + c];
    }
}

// ---------------- launch ----------------
extern "C" void kernel_launch(void* const* d_in, const int* in_sizes, int n_in,
                              void* d_out, int out_size) {
    const float* x        = (const float*)d_in[0];
    const float* norm1_w  = (const float*)d_in[1];
    const float* norm1_b  = (const float*)d_in[2];
    const float* qkv_w    = (const float*)d_in[3];
    const float* qkv_b    = (const float*)d_in[4];
    const float* pos_bias = (const float*)d_in[5];
    const float* out_w    = (const float*)d_in[6];
    const float* out_b    = (const float*)d_in[7];
    const float* convp_w  = (const float*)d_in[8];
    const float* convp_b  = (const float*)d_in[9];
    const float* pw1_w    = (const float*)d_in[10];
    const float* pw1_b    = (const float*)d_in[11];
    const float* dw1_w    = (const float*)d_in[12];
    const float* dw1_b    = (const float*)d_in[13];
    const float* tok_w    = (const float*)d_in[14];
    const float* tok_b    = (const float*)d_in[15];
    const float* norm2_w  = (const float*)d_in[16];
    const float* norm2_b  = (const float*)d_in[17];
    const float* lpw_w    = (const float*)d_in[18];
    const float* ldw_w    = (const float*)d_in[19];
    const float* ldw_b    = (const float*)d_in[20];
    const float* fc1_w    = (const float*)d_in[21];
    const float* fc1_b    = (const float*)d_in[22];
    const float* fc2_w    = (const float*)d_in[23];
    const float* fc2_b    = (const float*)d_in[24];
    float* out = (float*)d_out;

    const int SM_REMSA = 50176 + 17408 + 34816;           // 102400
    const int SM_LEFF  = 34816*3;                         // 104448
    cudaFuncSetAttribute(k_remsa, cudaFuncAttributeMaxDynamicSharedMemorySize, SM_REMSA);
    cudaFuncSetAttribute(k_leff,  cudaFuncAttributeMaxDynamicSharedMemorySize, SM_LEFF);

    k_prep <<<960,  256>>>(qkv_w, out_w, tok_w, lpw_w, fc1_w, fc2_w,
                           convp_w, convp_b, pw1_w, pw1_b);
    k_remsa<<<4096, 512, SM_REMSA>>>(x, norm1_w, norm1_b, qkv_b, pos_bias,
                                     out_b, tok_b, dw1_w, dw1_b, norm2_w, norm2_b);
    k_leff <<<2048, 512, SM_LEFF>>>(ldw_w, ldw_b, fc1_b, fc2_b, out);
}

// round 15
// speedup vs baseline: 1.0392x; 1.0392x over previous
#include <cuda_runtime.h>
#include <cuda_bf16.h>
#include <cstdint>
#include <math.h>

#define BATCH 4
#define CCH 128
#define NPIX (BATCH*256*256)     /* 262144 */
#define NWIN (NPIX/64)           /* 4096 */

// ---------------- device scratch ----------------
__device__ float g_bc[CCH];
// bf16 weight bank: [0..2]=qkv, [3]=Wc, [4]=out_w, [5]=tok_w, [6]=lpw,
// [7..10]=fc1 chunks, [11..14]=fc2 chunks. Each 128x128 row-major.
__device__ __nv_bfloat16 g_wbf[15*16384];
__device__ __nv_bfloat16 g_att[NPIX*CCH]; // remsa out bf16, window-token layout
__device__ float g_x1[NPIX*CCH];          // x + merged attn, channels-last fp32
__device__ __nv_bfloat16 g_z[NPIX*CCH];   // lpw out, channels-last bf16

// ---------------- helpers ----------------
__device__ __forceinline__ uint32_t bf2(float a, float b) {
    __nv_bfloat162 t = __floats2bfloat162_rn(a, b);
    return *reinterpret_cast<uint32_t*>(&t);
}
__device__ __forceinline__ float2 ubf2f(uint32_t w) {
    __nv_bfloat162 t = *reinterpret_cast<__nv_bfloat162*>(&w);
    return make_float2(__bfloat162float(t.x), __bfloat162float(t.y));
}

// exact-GELU via FMA-only erf polynomial (|z|<=1); rare tail uses erff
__device__ __forceinline__ float gelu_f(float v) {
    float z = v * 0.7071067811865475f;
    float e;
    if (fabsf(z) <= 1.0f) {
        float s = z*z;
        e = 7.853861595399774e-5f;
        e = e*s - 8.010193625184903e-4f;
        e = e*s + 5.188327685732524e-3f;
        e = e*s - 2.685381193529856e-2f;
        e = e*s + 1.128358514861418e-1f;
        e = e*s - 3.761262582423300e-1f;
        e = e*s + 1.128379165726710f;
        e = e*z;
    } else {
        e = erff(z);
    }
    return v * (0.5f + 0.5f*e);
}

__device__ __forceinline__ void mma16(float* c, const uint32_t* a, const uint32_t* b) {
    asm volatile(
        "mma.sync.aligned.m16n8k16.row.col.f32.bf16.bf16.f32 "
        "{%0,%1,%2,%3},{%4,%5,%6,%7},{%8,%9},{%0,%1,%2,%3};"
        : "+f"(c[0]), "+f"(c[1]), "+f"(c[2]), "+f"(c[3])
        : "r"(a[0]), "r"(a[1]), "r"(a[2]), "r"(a[3]), "r"(b[0]), "r"(b[1]));
}

#define LDSM4(R, addr) \
    asm volatile("ldmatrix.sync.aligned.m8n8.x4.shared.b16 {%0,%1,%2,%3}, [%4];" \
        : "=r"(R[0]), "=r"(R[1]), "=r"(R[2]), "=r"(R[3]) : "r"(addr))

// async stage: prepacked 128x128 bf16 weight -> smem [128][136]
__device__ __forceinline__ void stage_async(const __nv_bfloat16* __restrict__ Wb,
                                            __nv_bfloat16* __restrict__ sW, int tid) {
    uint32_t s = (uint32_t)__cvta_generic_to_shared(sW);
    const char* gp = (const char*)Wb;
    #pragma unroll
    for (int i = tid; i < 2048; i += 512) {
        int row = i >> 4, c8 = (i & 15) << 3;
        asm volatile("cp.async.cg.shared.global [%0], [%1], 16;"
            :: "r"(s + (uint32_t)(row*136 + c8)*2), "l"(gp + i*16));
    }
    asm volatile("cp.async.commit_group;" ::: "memory");
}
__device__ __forceinline__ void stage_wait0() {
    asm volatile("cp.async.wait_group 0;" ::: "memory");
}

// 128x128 GEMM tile, K=128, bf16 in, fp32 accum. 16 warps, each 32x32. ldmatrix loads.
__device__ __forceinline__ void mma_gemm16(const __nv_bfloat16* __restrict__ sA, int strideA,
                                           const __nv_bfloat16* __restrict__ sW,
                                           float acc[2][4][4], int warp, int lane) {
    int quad = lane >> 3, r = lane & 7;
    uint32_t aAddr = (uint32_t)__cvta_generic_to_shared(sA)
        + (uint32_t)((((warp & 3)*32 + (quad & 1)*8 + r) * strideA + (quad >> 1)*8) * 2);
    uint32_t bAddr = (uint32_t)__cvta_generic_to_shared(sW)
        + (uint32_t)((((warp >> 2)*32 + (quad >> 1)*8 + r) * 136 + (quad & 1)*8) * 2);
    uint32_t aStep = (uint32_t)(16 * strideA * 2);
    const uint32_t bStep = 16 * 136 * 2;
    #pragma unroll
    for (int kt = 0; kt < 8; ++kt) {
        uint32_t A0[4], A1[4], B0[4], B1[4];
        LDSM4(A0, aAddr);
        LDSM4(A1, aAddr + aStep);
        LDSM4(B0, bAddr);
        LDSM4(B1, bAddr + bStep);
        aAddr += 32; bAddr += 32;
        mma16(acc[0][0], A0, B0);     mma16(acc[0][1], A0, B0 + 2);
        mma16(acc[0][2], A0, B1);     mma16(acc[0][3], A0, B1 + 2);
        mma16(acc[1][0], A1, B0);     mma16(acc[1][1], A1, B0 + 2);
        mma16(acc[1][2], A1, B1);     mma16(acc[1][3], A1, B1 + 2);
    }
}

// Half-N variant: 128x(16-per-warp) columns — tacc is 16 regs, kills spills in leff.
__device__ __forceinline__ void mma_gemm16_n2(const __nv_bfloat16* __restrict__ sA, int strideA,
                                              const __nv_bfloat16* __restrict__ sW,
                                              float acc[2][2][4], int warp, int lane, int nhalf) {
    int quad = lane >> 3, r = lane & 7;
    uint32_t aAddr = (uint32_t)__cvta_generic_to_shared(sA)
        + (uint32_t)((((warp & 3)*32 + (quad & 1)*8 + r) * strideA + (quad >> 1)*8) * 2);
    uint32_t bAddr = (uint32_t)__cvta_generic_to_shared(sW)
        + (uint32_t)((((warp >> 2)*32 + nhalf*16 + (quad >> 1)*8 + r) * 136 + (quad & 1)*8) * 2);
    uint32_t aStep = (uint32_t)(16 * strideA * 2);
    #pragma unroll
    for (int kt = 0; kt < 8; ++kt) {
        uint32_t A0[4], A1[4], B0[4];
        LDSM4(A0, aAddr);
        LDSM4(A1, aAddr + aStep);
        LDSM4(B0, bAddr);
        aAddr += 32; bAddr += 32;
        mma16(acc[0][0], A0, B0);     mma16(acc[0][1], A0, B0 + 2);
        mma16(acc[1][0], A1, B0);     mma16(acc[1][1], A1, B0 + 2);
    }
}

// ---------------- K0: pack weights to bf16 bank (Wc fused inline) ----------------
__global__ void k_prep(const float* __restrict__ qkv_w, const float* __restrict__ out_w,
                       const float* __restrict__ tok_w, const float* __restrict__ lpw_w,
                       const float* __restrict__ fc1_w, const float* __restrict__ fc2_w,
                       const float* __restrict__ convp_w, const float* __restrict__ convp_b,
                       const float* __restrict__ pw1_w,   const float* __restrict__ pw1_b) {
    int idx = blockIdx.x*256 + threadIdx.x;
    int blk = idx >> 14;
    int m = idx & 16383;
    int c = m >> 7, k = m & 127;
    float v;
    if      (blk < 3)  v = qkv_w[blk*16384 + m];
    else if (blk == 3) {
        v = 0.f;
        for (int i = 0; i < CCH; ++i) v += pw1_w[c*CCH + i] * convp_w[i*CCH + k];
    }
    else if (blk == 4) v = out_w[m];
    else if (blk == 5) v = tok_w[m];
    else if (blk == 6) v = lpw_w[m];
    else if (blk < 11) v = fc1_w[(blk-7)*16384 + m];
    else               v = fc2_w[c*512 + (blk-11)*128 + k];
    g_wbf[idx] = __float2bfloat16(v);
    if (idx < CCH) {
        float b = pw1_b[idx];
        for (int i = 0; i < CCH; ++i) b += pw1_w[idx*CCH + i] * convp_b[i];
        g_bc[idx] = b;
    }
}

// ---------------- ReMSA (LN1 fused): 2 windows per CTA, 512 threads ----------------
__global__ void k_remsa(const float* __restrict__ x,
                        const float* __restrict__ n1w, const float* __restrict__ n1b,
                        const float* __restrict__ qkv_b, const float* __restrict__ pos_bias,
                        const float* __restrict__ out_b, const float* __restrict__ tok_b,
                        const float* __restrict__ dw1_w, const float* __restrict__ dw1_b) {
    extern __shared__ __align__(16) char smem[];
    __nv_bfloat16* s_qkv = (__nv_bfloat16*)smem;                   // 128*520 bf16 (also s_x fp32)
    __nv_bfloat16* s_y   = (__nv_bfloat16*)(smem + 133120);        // 128*136 (LN1 / ao)
    __nv_bfloat16* s_W   = (__nv_bfloat16*)(smem + 133120 + 34816);
    __shared__ float s_mu[128], s_rs[128];
    int tid = threadIdx.x, warp = tid >> 5, lane = tid & 31;
    int win0 = blockIdx.x * 2;
    int bb   = win0 >> 10;
    int rem  = win0 & 1023;
    int h0   = (rem >> 5) * 8;
    int w0c  = (rem & 31) * 8;   // 16 columns wide (2 windows)

    stage_async(g_wbf, s_W, tid);    // prefetch qkv chunk 0

    // ---- LN1 fused: load x tile (128 ch x 8 rows x 16 cols) into s_x fp32 ----
    float* s_x = (float*)s_qkv;      // [128 tokens][129]
    const float* xb = x + (size_t)bb*CCH*65536 + h0*256 + w0c;
    #pragma unroll
    for (int it = 0; it < 8; ++it) {
        int idx = tid + it*512;                 // 4096 float4
        int c = idx >> 5, r = (idx >> 2) & 7, w4 = idx & 3;
        float4 v = *(const float4*)(xb + c*65536 + r*256 + w4*4);
        int wb = w4*4;
        int row0 = (wb >> 3)*64 + r*8 + (wb & 7);
        s_x[(row0  )*129 + c] = v.x;
        s_x[(row0+1)*129 + c] = v.y;
        s_x[(row0+2)*129 + c] = v.z;
        s_x[(row0+3)*129 + c] = v.w;
    }
    __syncthreads();
    {
        int p = tid >> 2, q = tid & 3;
        float sm = 0.f, sq = 0.f;
        #pragma unroll
        for (int i = 0; i < 32; ++i) { float v = s_x[p*129 + q*32 + i]; sm += v; sq += v*v; }
        sm += __shfl_xor_sync(0xffffffffu, sm, 1); sq += __shfl_xor_sync(0xffffffffu, sq, 1);
        sm += __shfl_xor_sync(0xffffffffu, sm, 2); sq += __shfl_xor_sync(0xffffffffu, sq, 2);
        if (q == 0) {
            float mu = sm * (1.f/128.f);
            float var = sq * (1.f/128.f) - mu*mu;
            s_mu[p] = mu; s_rs[p] = rsqrtf(var + 1e-5f);
        }
    }
    __syncthreads();
    uint32_t* s_yw = (uint32_t*)s_y;
    for (int idx = tid; idx < 8192; idx += 512) {
        int pp = idx >> 6, cw = idx & 63, c0 = cw*2;
        float mu = s_mu[pp], rs = s_rs[pp];
        float v0 = (s_x[pp*129 + c0]   - mu) * rs * n1w[c0]   + n1b[c0];
        float v1 = (s_x[pp*129 + c0+1] - mu) * rs * n1w[c0+1] + n1b[c0+1];
        s_yw[pp*68 + cw] = bf2(v0, v1);
    }

    int g = lane >> 2, tg = lane & 3;
    int rbase = (warp & 3) * 32 + g;
    int cbase = (warp >> 2) * 32;
    uint32_t* qw = (uint32_t*)s_qkv;   // stride 260 words per row (overwrites s_x)

    // Phase A: [qkv ; Wc] GEMM (128 x 512) -> s_qkv bf16
    for (int chunk = 0; chunk < 4; ++chunk) {
        stage_wait0();
        __syncthreads();
        float acc[2][4][4] = {};
        mma_gemm16(s_y, 136, s_W, acc, warp, lane);
        __syncthreads();
        if (chunk < 3) stage_async(g_wbf + (chunk+1)*16384, s_W, tid);
        const float* bsrc = (chunk < 3) ? (qkv_b + chunk*128) : g_bc;
        #pragma unroll
        for (int mt = 0; mt < 2; ++mt)
            #pragma unroll
            for (int nt = 0; nt < 4; ++nt) {
                int r0 = rbase + mt*16;
                int c0 = cbase + nt*8 + 2*tg;
                float b0 = bsrc[c0], b1 = bsrc[c0+1];
                int off = chunk*64 + (c0 >> 1);
                qw[ r0   *260 + off] = bf2(acc[mt][nt][0] + b0, acc[mt][nt][1] + b1);
                qw[(r0+8)*260 + off] = bf2(acc[mt][nt][2] + b0, acc[mt][nt][3] + b1);
            }
    }
    __syncthreads();

    // Phase B: head-mixing attention; 4 threads/token, 2 heads each; ao -> s_y
    {
        int r = tid >> 2, q4 = tid & 3, n = r & 63;
        const uint32_t* base = qw + r*260;
        const float* pb = pos_bias + n*64;
        uint32_t* aw = (uint32_t*)s_y;
        #pragma unroll
        for (int hh = 0; hh < 2; ++hh) {
            int hI = q4*2 + hh;
            float qv[16];
            #pragma unroll
            for (int d = 0; d < 8; ++d) {
                float2 f = ubf2f(base[hI*24 + d]);
                qv[2*d] = f.x; qv[2*d+1] = f.y;
            }
            float sc[8]; float mx = -1e30f;
            #pragma unroll
            for (int gg = 0; gg < 8; ++gg) {
                const uint32_t* kp = base + gg*24 + 8;
                float sd = 0.f;
                #pragma unroll
                for (int d = 0; d < 8; ++d) {
                    float2 f = ubf2f(kp[d]);
                    sd += qv[2*d]*f.x + qv[2*d+1]*f.y;
                }
                sc[gg] = sd*0.25f + pb[hI*8 + gg];
                mx = fmaxf(mx, sc[gg]);
            }
            float ssum = 0.f;
            #pragma unroll
            for (int gg = 0; gg < 8; ++gg) { sc[gg] = __expf(sc[gg] - mx); ssum += sc[gg]; }
            float inv = 1.f / ssum;
            float ao[16];
            #pragma unroll
            for (int d = 0; d < 16; ++d) ao[d] = 0.f;
            #pragma unroll
            for (int gg = 0; gg < 8; ++gg) {
                float a = sc[gg]*inv;
                const uint32_t* vp = base + gg*24 + 16;
                #pragma unroll
                for (int d = 0; d < 8; ++d) {
                    float2 f = ubf2f(vp[d]);
                    ao[2*d]   += a*f.x;
                    ao[2*d+1] += a*f.y;
                }
            }
            #pragma unroll
            for (int d = 0; d < 8; ++d)
                aw[r*68 + hI*8 + d] = bf2(ao[2*d], ao[2*d+1]);
        }
    }

    // Phase C: token-dim dwconv on xc; read->regs, sync, write cols 0..63
    uint32_t cres[16];
    #pragma unroll
    for (int it = 0; it < 16; ++it) {
        int idx = tid + it*512;
        int r = idx >> 6, cw = idx & 63, n = r & 63;
        int c0 = cw*2;
        float2 m  = ubf2f(qw[r*260 + 192 + cw]);
        float2 lo = make_float2(0.f, 0.f), hi = make_float2(0.f, 0.f);
        if (n > 0)  lo = ubf2f(qw[(r-1)*260 + 192 + cw]);
        if (n < 63) hi = ubf2f(qw[(r+1)*260 + 192 + cw]);
        float d0 = lo.x*dw1_w[c0*3]   + m.x*dw1_w[c0*3+1] + hi.x*dw1_w[c0*3+2] + dw1_b[c0];
        float d1 = lo.y*dw1_w[c0*3+3] + m.y*dw1_w[c0*3+4] + hi.y*dw1_w[c0*3+5] + dw1_b[c0+1];
        cres[it] = bf2(d0, d1);
    }
    __syncthreads();
    stage_async(g_wbf + 4*16384, s_W, tid);   // out_w behind Phase C writes
    #pragma unroll
    for (int it = 0; it < 16; ++it) {
        int idx = tid + it*512;
        qw[(idx >> 6)*260 + (idx & 63)] = cres[it];
    }
    stage_wait0();
    __syncthreads();

    // Phase D: ao @ out_w^T + dconv @ tok_w^T -> g_att (bf16)
    float acc[2][4][4] = {};
    mma_gemm16(s_y, 136, s_W, acc, warp, lane);
    __syncthreads();
    stage_async(g_wbf + 5*16384, s_W, tid);
    stage_wait0();
    __syncthreads();
    mma_gemm16(s_qkv, 520, s_W, acc, warp, lane);
    uint32_t* ow = (uint32_t*)g_att + (size_t)win0*4096;
    #pragma unroll
    for (int mt = 0; mt < 2; ++mt)
        #pragma unroll
        for (int nt = 0; nt < 4; ++nt) {
            int r0 = rbase + mt*16;
            int c0 = cbase + nt*8 + 2*tg;
            float b0 = out_b[c0] + tok_b[c0], b1 = out_b[c0+1] + tok_b[c0+1];
            ow[ r0   *64 + (c0 >> 1)] = bf2(acc[mt][nt][0] + b0, acc[mt][nt][1] + b1);
            ow[(r0+8)*64 + (c0 >> 1)] = bf2(acc[mt][nt][2] + b0, acc[mt][nt][3] + b1);
        }
}

// ---------------- LN2 + lpw fused: register-resident, 2 CTAs/SM ----------------
__global__ void __launch_bounds__(512, 2) k_ln2z(const float* __restrict__ x,
                                                 const float* __restrict__ w,
                                                 const float* __restrict__ b) {
    extern __shared__ __align__(16) char smem[];
    __nv_bfloat16* s_A = (__nv_bfloat16*)smem;            // 128*136
    __nv_bfloat16* s_W = (__nv_bfloat16*)(smem + 34816);  // 128*136
    int tid = threadIdx.x, bid = blockIdx.x;
    int warp = tid >> 5, lane = tid & 31;
    int w0 = (bid & 1) * 128;
    int h  = (bid >> 1) & 255;
    int bb = bid >> 9;
    stage_async(g_wbf + 6*16384, s_W, tid);

    int p = tid >> 2, q = tid & 3;
    int wc = w0 + p;
    const float* xp = x + (size_t)bb*CCH*65536 + h*256 + wc + (size_t)q*32*65536;
    float x1[32];
    #pragma unroll
    for (int i = 0; i < 32; ++i) x1[i] = xp[(size_t)i*65536];
    int win = (bb*32 + (h >> 3))*32 + (wc >> 3);
    int n   = (h & 7)*8 + (wc & 7);
    const uint4* ap = (const uint4*)((const uint32_t*)g_att + (size_t)win*4096 + n*64 + q*16);
    #pragma unroll
    for (int j4 = 0; j4 < 4; ++j4) {
        uint4 u = ap[j4];
        float2 f;
        f = ubf2f(u.x); x1[j4*8+0] += f.x; x1[j4*8+1] += f.y;
        f = ubf2f(u.y); x1[j4*8+2] += f.x; x1[j4*8+3] += f.y;
        f = ubf2f(u.z); x1[j4*8+4] += f.x; x1[j4*8+5] += f.y;
        f = ubf2f(u.w); x1[j4*8+6] += f.x; x1[j4*8+7] += f.y;
    }
    float* xo = g_x1 + ((size_t)(bb*65536 + h*256 + wc))*128 + q*32;
    #pragma unroll
    for (int i = 0; i < 8; ++i)
        *(float4*)(xo + i*4) = make_float4(x1[4*i], x1[4*i+1], x1[4*i+2], x1[4*i+3]);
    float sm = 0.f, sq = 0.f;
    #pragma unroll
    for (int i = 0; i < 32; ++i) { sm += x1[i]; sq += x1[i]*x1[i]; }
    sm += __shfl_xor_sync(0xffffffffu, sm, 1); sq += __shfl_xor_sync(0xffffffffu, sq, 1);
    sm += __shfl_xor_sync(0xffffffffu, sm, 2); sq += __shfl_xor_sync(0xffffffffu, sq, 2);
    float mu = sm * (1.f/128.f);
    float rs = rsqrtf(sq * (1.f/128.f) - mu*mu + 1e-5f);
    uint32_t* aw = (uint32_t*)s_A;
    #pragma unroll
    for (int j = 0; j < 16; ++j) {
        int c0 = q*32 + 2*j;
        float v0 = (x1[2*j]   - mu) * rs * w[c0]   + b[c0];
        float v1 = (x1[2*j+1] - mu) * rs * w[c0+1] + b[c0+1];
        aw[p*68 + q*16 + j] = bf2(v0, v1);
    }
    stage_wait0();
    __syncthreads();
    float acc[2][4][4] = {};
    mma_gemm16(s_A, 136, s_W, acc, warp, lane);
    int g = lane >> 2, tg = lane & 3;
    int rbase = (warp & 3) * 32 + g;
    int cbase = (warp >> 2) * 32;
    size_t pixb = (size_t)(bb*65536 + h*256 + w0);
    uint32_t* zw = (uint32_t*)g_z;
    #pragma unroll
    for (int mt = 0; mt < 2; ++mt)
        #pragma unroll
        for (int nt = 0; nt < 4; ++nt) {
            int r0 = rbase + mt*16;
            int c0 = cbase + nt*8 + 2*tg;
            zw[(pixb + r0)  *64 + (c0 >> 1)] = bf2(acc[mt][nt][0], acc[mt][nt][1]);
            zw[(pixb + r0+8)*64 + (c0 >> 1)] = bf2(acc[mt][nt][2], acc[mt][nt][3]);
        }
}

// ---------------- LeFF: 128 pixels per CTA, 512 threads, 2 CTAs/SM, overlapped fc2 stage ----------------
__global__ void __launch_bounds__(512, 2) k_leff(const float* __restrict__ ldw_w,
                                                 const float* __restrict__ ldw_b,
                                                 const float* __restrict__ fc1_b,
                                                 const float* __restrict__ fc2_b,
                                                 float* __restrict__ out) {
    extern __shared__ __align__(16) char smem[];
    __nv_bfloat16* s_d = (__nv_bfloat16*)smem;                   // 128*136
    __nv_bfloat16* s_t = (__nv_bfloat16*)(smem + 34816);         // 128*136
    __nv_bfloat16* s_W = (__nv_bfloat16*)(smem + 69632);         // 128*136
    float* s_f = (float*)(smem + 34816);                         // aliases s_t + s_W
    int tid = threadIdx.x, warp = tid >> 5, lane = tid & 31, bid = blockIdx.x;
    int w0 = (bid & 1) * 128;
    int h  = (bid >> 1) & 255;
    int bb = bid >> 9;

    stage_async(g_wbf + 7*16384, s_W, tid);    // fc1[0]

    // 3x3 depthwise over g_z (bf16 channels-last), uint4-vectorized (8 channels/thread)
    {
        const uint4* zw4 = (const uint4*)g_z;
        #pragma unroll
        for (int it = 0; it < 4; ++it) {
            int idx = tid + it*512;              // 2048 uint4
            int p = idx >> 4, c16 = idx & 15;
            int c0 = c16*8;
            int xx0 = w0 + p;
            float acc[8];
            #pragma unroll
            for (int j = 0; j < 8; ++j) acc[j] = ldw_b[c0 + j];
            #pragma unroll
            for (int dy = 0; dy < 3; ++dy) {
                int yy = h + dy - 1;
                if (yy < 0 || yy > 255) continue;
                #pragma unroll
                for (int dx = 0; dx < 3; ++dx) {
                    int xx = xx0 + dx - 1;
                    if (xx < 0 || xx > 255) continue;
                    uint4 u = zw4[((size_t)(bb*65536 + yy*256 + xx))*16 + c16];
                    float2 f;
                    f = ubf2f(u.x); acc[0] += f.x*ldw_w[(c0  )*9 + dy*3 + dx];
                                    acc[1] += f.y*ldw_w[(c0+1)*9 + dy*3 + dx];
                    f = ubf2f(u.y); acc[2] += f.x*ldw_w[(c0+2)*9 + dy*3 + dx];
                                    acc[3] += f.y*ldw_w[(c0+3)*9 + dy*3 + dx];
                    f = ubf2f(u.z); acc[4] += f.x*ldw_w[(c0+4)*9 + dy*3 + dx];
                                    acc[5] += f.y*ldw_w[(c0+5)*9 + dy*3 + dx];
                    f = ubf2f(u.w); acc[6] += f.x*ldw_w[(c0+6)*9 + dy*3 + dx];
                                    acc[7] += f.y*ldw_w[(c0+7)*9 + dy*3 + dx];
                }
            }
            uint4 o;
            o.x = bf2(acc[0], acc[1]); o.y = bf2(acc[2], acc[3]);
            o.z = bf2(acc[4], acc[5]); o.w = bf2(acc[6], acc[7]);
            *(uint4*)((uint32_t*)s_d + p*68 + c16*4) = o;
        }
    }

    int g = lane >> 2, tg = lane & 3;
    int rbase = (warp & 3) * 32 + g;
    int cbase = (warp >> 2) * 32;
    float oacc[2][4][4] = {};
    for (int jc = 0; jc < 4; ++jc) {
        stage_wait0();                       // fc1[jc] landed
        __syncthreads();
        uint32_t* tw = (uint32_t*)s_t;
        // half 0: MMA + gelu + store
        {
            float tacc[2][2][4] = {};
            mma_gemm16_n2(s_d, 136, s_W, tacc, warp, lane, 0);
            #pragma unroll
            for (int mt = 0; mt < 2; ++mt)
                #pragma unroll
                for (int nt = 0; nt < 2; ++nt) {
                    int r0 = rbase + mt*16;
                    int c0 = cbase + nt*8 + 2*tg;
                    float b0 = fc1_b[jc*128 + c0], b1 = fc1_b[jc*128 + c0 + 1];
                    float v0 = gelu_f(tacc[mt][nt][0] + b0);
                    float v1 = gelu_f(tacc[mt][nt][1] + b1);
                    float v2 = gelu_f(tacc[mt][nt][2] + b0);
                    float v3 = gelu_f(tacc[mt][nt][3] + b1);
                    tw[ r0   *68 + (c0 >> 1)] = bf2(v0, v1);
                    tw[(r0+8)*68 + (c0 >> 1)] = bf2(v2, v3);
                }
        }
        // half 1: MMA now; gelu AFTER issuing the fc2 stage so the load overlaps it
        {
            float tacc[2][2][4] = {};
            mma_gemm16_n2(s_d, 136, s_W, tacc, warp, lane, 1);
            __syncthreads();                             // all s_W reads retired
            stage_async(g_wbf + (11+jc)*16384, s_W, tid); // fc2[jc] flies under the gelu below
            #pragma unroll
            for (int mt = 0; mt < 2; ++mt)
                #pragma unroll
                for (int nt = 0; nt < 2; ++nt) {
                    int r0 = rbase + mt*16;
                    int c0 = cbase + 16 + nt*8 + 2*tg;
                    float b0 = fc1_b[jc*128 + c0], b1 = fc1_b[jc*128 + c0 + 1];
                    float v0 = gelu_f(tacc[mt][nt][0] + b0);
                    float v1 = gelu_f(tacc[mt][nt][1] + b1);
                    float v2 = gelu_f(tacc[mt][nt][2] + b0);
                    float v3 = gelu_f(tacc[mt][nt][3] + b1);
                    tw[ r0   *68 + (c0 >> 1)] = bf2(v0, v1);
                    tw[(r0+8)*68 + (c0 >> 1)] = bf2(v2, v3);
                }
        }
        stage_wait0();
        __syncthreads();                     // s_t complete + fc2 weights ready
        mma_gemm16(s_t, 136, s_W, oacc, warp, lane);
        __syncthreads();                     // fc2 weight + s_t reads done
        if (jc < 3) stage_async(g_wbf + (8+jc)*16384, s_W, tid);   // fc1[jc+1]
    }

    // epilogue: + fc2_b + residual x1 (fp32), stage fp32, transpose-write NCHW
    size_t pixb = (size_t)(bb*65536 + h*256 + w0);
    #pragma unroll
    for (int mt = 0; mt < 2; ++mt)
        #pragma unroll
        for (int nt = 0; nt < 4; ++nt) {
            int r0 = rbase + mt*16;
            int c0 = cbase + nt*8 + 2*tg;
            float b0 = fc2_b[c0], b1 = fc2_b[c0+1];
            float2 x0 = *(const float2*)&g_x1[(pixb + r0)  *128 + c0];
            float2 x1 = *(const float2*)&g_x1[(pixb + r0+8)*128 + c0];
            s_f[ r0   *129 + c0]     = oacc[mt][nt][0] + b0 + x0.x;
            s_f[ r0   *129 + c0 + 1] = oacc[mt][nt][1] + b1 + x0.y;
            s_f[(r0+8)*129 + c0]     = oacc[mt][nt][2] + b0 + x1.x;
            s_f[(r0+8)*129 + c0 + 1] = oacc[mt][nt][3] + b1 + x1.y;
        }
    __syncthreads();
    for (int idx = tid; idx < 16384; idx += 512) {
        int c = idx >> 7, p = idx & 127;
        out[((size_t)(bb*128 + c)*256 + h)*256 + w0 + p] = s_f[p*129 + c];
    }
}

// ---------------- launch ----------------
extern "C" void kernel_launch(void* const* d_in, const int* in_sizes, int n_in,
                              void* d_out, int out_size) {
    const float* x        = (const float*)d_in[0];
    const float* norm1_w  = (const float*)d_in[1];
    const float* norm1_b  = (const float*)d_in[2];
    const float* qkv_w    = (const float*)d_in[3];
    const float* qkv_b    = (const float*)d_in[4];
    const float* pos_bias = (const float*)d_in[5];
    const float* out_w    = (const float*)d_in[6];
    const float* out_b    = (const float*)d_in[7];
    const float* convp_w  = (const float*)d_in[8];
    const float* convp_b  = (const float*)d_in[9];
    const float* pw1_w    = (const float*)d_in[10];
    const float* pw1_b    = (const float*)d_in[11];
    const float* dw1_w    = (const float*)d_in[12];
    const float* dw1_b    = (const float*)d_in[13];
    const float* tok_w    = (const float*)d_in[14];
    const float* tok_b    = (const float*)d_in[15];
    const float* norm2_w  = (const float*)d_in[16];
    const float* norm2_b  = (const float*)d_in[17];
    const float* lpw_w    = (const float*)d_in[18];
    const float* ldw_w    = (const float*)d_in[19];
    const float* ldw_b    = (const float*)d_in[20];
    const float* fc1_w    = (const float*)d_in[21];
    const float* fc1_b    = (const float*)d_in[22];
    const float* fc2_w    = (const float*)d_in[23];
    const float* fc2_b    = (const float*)d_in[24];
    float* out = (float*)d_out;

    const int SM_REMSA = 133120 + 34816 + 34816;          // 202752
    const int SM_LN2Z  = 34816 + 34816;                   //  69632
    const int SM_LEFF  = 34816*3;                         // 104448
    cudaFuncSetAttribute(k_remsa, cudaFuncAttributeMaxDynamicSharedMemorySize, SM_REMSA);
    cudaFuncSetAttribute(k_ln2z,  cudaFuncAttributeMaxDynamicSharedMemorySize, SM_LN2Z);
    cudaFuncSetAttribute(k_leff,  cudaFuncAttributeMaxDynamicSharedMemorySize, SM_LEFF);

    k_prep <<<960,  256>>>(qkv_w, out_w, tok_w, lpw_w, fc1_w, fc2_w,
                           convp_w, convp_b, pw1_w, pw1_b);
    k_remsa<<<2048, 512, SM_REMSA>>>(x, norm1_w, norm1_b, qkv_b, pos_bias,
                                     out_b, tok_b, dw1_w, dw1_b);
    k_ln2z <<<2048, 512, SM_LN2Z>>>(x, norm2_w, norm2_b);
    k_leff <<<2048, 512, SM_LEFF>>>(ldw_w, ldw_b, fc1_b, fc2_b, out);
}

// round 16
// speedup vs baseline: 1.0640x; 1.0239x over previous
#include <cuda_runtime.h>
#include <cuda_bf16.h>
#include <cstdint>
#include <math.h>

#define BATCH 4
#define CCH 128
#define NPIX (BATCH*256*256)     /* 262144 */
#define NWIN (NPIX/64)           /* 4096 */

// ---------------- device scratch ----------------
__device__ float g_bc[CCH];
// bf16 weight bank: [0..2]=qkv, [3]=Wc, [4]=out_w, [5]=tok_w, [6]=lpw,
// [7..10]=fc1 chunks, [11..14]=fc2 chunks. Each 128x128 row-major.
__device__ __nv_bfloat16 g_wbf[15*16384];
__device__ __nv_bfloat16 g_att[NPIX*CCH]; // remsa out bf16, window-token layout
__device__ __nv_bfloat16 g_z[NPIX*CCH];   // lpw out, channels-last bf16

// ---------------- helpers ----------------
__device__ __forceinline__ uint32_t bf2(float a, float b) {
    __nv_bfloat162 t = __floats2bfloat162_rn(a, b);
    return *reinterpret_cast<uint32_t*>(&t);
}
__device__ __forceinline__ float2 ubf2f(uint32_t w) {
    __nv_bfloat162 t = *reinterpret_cast<__nv_bfloat162*>(&w);
    return make_float2(__bfloat162float(t.x), __bfloat162float(t.y));
}

// exact-GELU via FMA-only erf polynomial (|z|<=1); rare tail uses erff
__device__ __forceinline__ float gelu_f(float v) {
    float z = v * 0.7071067811865475f;
    float e;
    if (fabsf(z) <= 1.0f) {
        float s = z*z;
        e = 7.853861595399774e-5f;
        e = e*s - 8.010193625184903e-4f;
        e = e*s + 5.188327685732524e-3f;
        e = e*s - 2.685381193529856e-2f;
        e = e*s + 1.128358514861418e-1f;
        e = e*s - 3.761262582423300e-1f;
        e = e*s + 1.128379165726710f;
        e = e*z;
    } else {
        e = erff(z);
    }
    return v * (0.5f + 0.5f*e);
}

__device__ __forceinline__ void mma16(float* c, const uint32_t* a, const uint32_t* b) {
    asm volatile(
        "mma.sync.aligned.m16n8k16.row.col.f32.bf16.bf16.f32 "
        "{%0,%1,%2,%3},{%4,%5,%6,%7},{%8,%9},{%0,%1,%2,%3};"
        : "+f"(c[0]), "+f"(c[1]), "+f"(c[2]), "+f"(c[3])
        : "r"(a[0]), "r"(a[1]), "r"(a[2]), "r"(a[3]), "r"(b[0]), "r"(b[1]));
}

#define LDSM4(R, addr) \
    asm volatile("ldmatrix.sync.aligned.m8n8.x4.shared.b16 {%0,%1,%2,%3}, [%4];" \
        : "=r"(R[0]), "=r"(R[1]), "=r"(R[2]), "=r"(R[3]) : "r"(addr))

// async stage: prepacked 128x128 bf16 weight -> smem [128][136]
__device__ __forceinline__ void stage_async(const __nv_bfloat16* __restrict__ Wb,
                                            __nv_bfloat16* __restrict__ sW, int tid) {
    uint32_t s = (uint32_t)__cvta_generic_to_shared(sW);
    const char* gp = (const char*)Wb;
    #pragma unroll
    for (int i = tid; i < 2048; i += 512) {
        int row = i >> 4, c8 = (i & 15) << 3;
        asm volatile("cp.async.cg.shared.global [%0], [%1], 16;"
            :: "r"(s + (uint32_t)(row*136 + c8)*2), "l"(gp + i*16));
    }
    asm volatile("cp.async.commit_group;" ::: "memory");
}
__device__ __forceinline__ void stage_wait0() {
    asm volatile("cp.async.wait_group 0;" ::: "memory");
}

// 128x128 GEMM tile, K=128, bf16 in, fp32 accum. 16 warps, each 32x32. ldmatrix loads.
__device__ __forceinline__ void mma_gemm16(const __nv_bfloat16* __restrict__ sA, int strideA,
                                           const __nv_bfloat16* __restrict__ sW,
                                           float acc[2][4][4], int warp, int lane) {
    int quad = lane >> 3, r = lane & 7;
    uint32_t aAddr = (uint32_t)__cvta_generic_to_shared(sA)
        + (uint32_t)((((warp & 3)*32 + (quad & 1)*8 + r) * strideA + (quad >> 1)*8) * 2);
    uint32_t bAddr = (uint32_t)__cvta_generic_to_shared(sW)
        + (uint32_t)((((warp >> 2)*32 + (quad >> 1)*8 + r) * 136 + (quad & 1)*8) * 2);
    uint32_t aStep = (uint32_t)(16 * strideA * 2);
    const uint32_t bStep = 16 * 136 * 2;
    #pragma unroll
    for (int kt = 0; kt < 8; ++kt) {
        uint32_t A0[4], A1[4], B0[4], B1[4];
        LDSM4(A0, aAddr);
        LDSM4(A1, aAddr + aStep);
        LDSM4(B0, bAddr);
        LDSM4(B1, bAddr + bStep);
        aAddr += 32; bAddr += 32;
        mma16(acc[0][0], A0, B0);     mma16(acc[0][1], A0, B0 + 2);
        mma16(acc[0][2], A0, B1);     mma16(acc[0][3], A0, B1 + 2);
        mma16(acc[1][0], A1, B0);     mma16(acc[1][1], A1, B0 + 2);
        mma16(acc[1][2], A1, B1);     mma16(acc[1][3], A1, B1 + 2);
    }
}

// Half-N variant: 128x(16-per-warp) columns — tacc is 16 regs, kills spills in leff.
__device__ __forceinline__ void mma_gemm16_n2(const __nv_bfloat16* __restrict__ sA, int strideA,
                                              const __nv_bfloat16* __restrict__ sW,
                                              float acc[2][2][4], int warp, int lane, int nhalf) {
    int quad = lane >> 3, r = lane & 7;
    uint32_t aAddr = (uint32_t)__cvta_generic_to_shared(sA)
        + (uint32_t)((((warp & 3)*32 + (quad & 1)*8 + r) * strideA + (quad >> 1)*8) * 2);
    uint32_t bAddr = (uint32_t)__cvta_generic_to_shared(sW)
        + (uint32_t)((((warp >> 2)*32 + nhalf*16 + (quad >> 1)*8 + r) * 136 + (quad & 1)*8) * 2);
    uint32_t aStep = (uint32_t)(16 * strideA * 2);
    #pragma unroll
    for (int kt = 0; kt < 8; ++kt) {
        uint32_t A0[4], A1[4], B0[4];
        LDSM4(A0, aAddr);
        LDSM4(A1, aAddr + aStep);
        LDSM4(B0, bAddr);
        aAddr += 32; bAddr += 32;
        mma16(acc[0][0], A0, B0);     mma16(acc[0][1], A0, B0 + 2);
        mma16(acc[1][0], A1, B0);     mma16(acc[1][1], A1, B0 + 2);
    }
}

// ---------------- K0: pack weights to bf16 bank (Wc fused inline) ----------------
__global__ void k_prep(const float* __restrict__ qkv_w, const float* __restrict__ out_w,
                       const float* __restrict__ tok_w, const float* __restrict__ lpw_w,
                       const float* __restrict__ fc1_w, const float* __restrict__ fc2_w,
                       const float* __restrict__ convp_w, const float* __restrict__ convp_b,
                       const float* __restrict__ pw1_w,   const float* __restrict__ pw1_b) {
    int idx = blockIdx.x*256 + threadIdx.x;
    int blk = idx >> 14;
    int m = idx & 16383;
    int c = m >> 7, k = m & 127;
    float v;
    if      (blk < 3)  v = qkv_w[blk*16384 + m];
    else if (blk == 3) {
        v = 0.f;
        for (int i = 0; i < CCH; ++i) v += pw1_w[c*CCH + i] * convp_w[i*CCH + k];
    }
    else if (blk == 4) v = out_w[m];
    else if (blk == 5) v = tok_w[m];
    else if (blk == 6) v = lpw_w[m];
    else if (blk < 11) v = fc1_w[(blk-7)*16384 + m];
    else               v = fc2_w[c*512 + (blk-11)*128 + k];
    g_wbf[idx] = __float2bfloat16(v);
    if (idx < CCH) {
        float b = pw1_b[idx];
        for (int i = 0; i < CCH; ++i) b += pw1_w[idx*CCH + i] * convp_b[i];
        g_bc[idx] = b;
    }
}

// ---------------- ReMSA (LN1 fused): 2 windows per CTA, 512 threads ----------------
__global__ void k_remsa(const float* __restrict__ x,
                        const float* __restrict__ n1w, const float* __restrict__ n1b,
                        const float* __restrict__ qkv_b, const float* __restrict__ pos_bias,
                        const float* __restrict__ out_b, const float* __restrict__ tok_b,
                        const float* __restrict__ dw1_w, const float* __restrict__ dw1_b) {
    extern __shared__ __align__(16) char smem[];
    __nv_bfloat16* s_qkv = (__nv_bfloat16*)smem;                   // 128*520 bf16 (also s_x fp32)
    __nv_bfloat16* s_y   = (__nv_bfloat16*)(smem + 133120);        // 128*136 (LN1 / ao)
    __nv_bfloat16* s_W   = (__nv_bfloat16*)(smem + 133120 + 34816);
    __shared__ float s_mu[128], s_rs[128];
    int tid = threadIdx.x, warp = tid >> 5, lane = tid & 31;
    int win0 = blockIdx.x * 2;
    int bb   = win0 >> 10;
    int rem  = win0 & 1023;
    int h0   = (rem >> 5) * 8;
    int w0c  = (rem & 31) * 8;   // 16 columns wide (2 windows)

    stage_async(g_wbf, s_W, tid);    // prefetch qkv chunk 0

    // ---- LN1 fused: load x tile (128 ch x 8 rows x 16 cols) into s_x fp32 ----
    float* s_x = (float*)s_qkv;      // [128 tokens][129]
    const float* xb = x + (size_t)bb*CCH*65536 + h0*256 + w0c;
    #pragma unroll
    for (int it = 0; it < 8; ++it) {
        int idx = tid + it*512;                 // 4096 float4
        int c = idx >> 5, r = (idx >> 2) & 7, w4 = idx & 3;
        float4 v = *(const float4*)(xb + c*65536 + r*256 + w4*4);
        int wb = w4*4;
        int row0 = (wb >> 3)*64 + r*8 + (wb & 7);
        s_x[(row0  )*129 + c] = v.x;
        s_x[(row0+1)*129 + c] = v.y;
        s_x[(row0+2)*129 + c] = v.z;
        s_x[(row0+3)*129 + c] = v.w;
    }
    __syncthreads();
    {
        int p = tid >> 2, q = tid & 3;
        float sm = 0.f, sq = 0.f;
        #pragma unroll
        for (int i = 0; i < 32; ++i) { float v = s_x[p*129 + q*32 + i]; sm += v; sq += v*v; }
        sm += __shfl_xor_sync(0xffffffffu, sm, 1); sq += __shfl_xor_sync(0xffffffffu, sq, 1);
        sm += __shfl_xor_sync(0xffffffffu, sm, 2); sq += __shfl_xor_sync(0xffffffffu, sq, 2);
        if (q == 0) {
            float mu = sm * (1.f/128.f);
            float var = sq * (1.f/128.f) - mu*mu;
            s_mu[p] = mu; s_rs[p] = rsqrtf(var + 1e-5f);
        }
    }
    __syncthreads();
    uint32_t* s_yw = (uint32_t*)s_y;
    for (int idx = tid; idx < 8192; idx += 512) {
        int pp = idx >> 6, cw = idx & 63, c0 = cw*2;
        float mu = s_mu[pp], rs = s_rs[pp];
        float v0 = (s_x[pp*129 + c0]   - mu) * rs * n1w[c0]   + n1b[c0];
        float v1 = (s_x[pp*129 + c0+1] - mu) * rs * n1w[c0+1] + n1b[c0+1];
        s_yw[pp*68 + cw] = bf2(v0, v1);
    }

    int g = lane >> 2, tg = lane & 3;
    int rbase = (warp & 3) * 32 + g;
    int cbase = (warp >> 2) * 32;
    uint32_t* qw = (uint32_t*)s_qkv;   // stride 260 words per row (overwrites s_x)

    // Phase A: [qkv ; Wc] GEMM (128 x 512) -> s_qkv bf16
    for (int chunk = 0; chunk < 4; ++chunk) {
        stage_wait0();
        __syncthreads();
        float acc[2][4][4] = {};
        mma_gemm16(s_y, 136, s_W, acc, warp, lane);
        __syncthreads();
        if (chunk < 3) stage_async(g_wbf + (chunk+1)*16384, s_W, tid);
        const float* bsrc = (chunk < 3) ? (qkv_b + chunk*128) : g_bc;
        #pragma unroll
        for (int mt = 0; mt < 2; ++mt)
            #pragma unroll
            for (int nt = 0; nt < 4; ++nt) {
                int r0 = rbase + mt*16;
                int c0 = cbase + nt*8 + 2*tg;
                float b0 = bsrc[c0], b1 = bsrc[c0+1];
                int off = chunk*64 + (c0 >> 1);
                qw[ r0   *260 + off] = bf2(acc[mt][nt][0] + b0, acc[mt][nt][1] + b1);
                qw[(r0+8)*260 + off] = bf2(acc[mt][nt][2] + b0, acc[mt][nt][3] + b1);
            }
    }
    __syncthreads();

    // Phase B: head-mixing attention; 4 threads/token, 2 heads each; ao -> s_y
    {
        int r = tid >> 2, q4 = tid & 3, n = r & 63;
        const uint32_t* base = qw + r*260;
        const float* pb = pos_bias + n*64;
        uint32_t* aw = (uint32_t*)s_y;
        #pragma unroll
        for (int hh = 0; hh < 2; ++hh) {
            int hI = q4*2 + hh;
            float qv[16];
            #pragma unroll
            for (int d = 0; d < 8; ++d) {
                float2 f = ubf2f(base[hI*24 + d]);
                qv[2*d] = f.x; qv[2*d+1] = f.y;
            }
            float sc[8]; float mx = -1e30f;
            #pragma unroll
            for (int gg = 0; gg < 8; ++gg) {
                const uint32_t* kp = base + gg*24 + 8;
                float sd = 0.f;
                #pragma unroll
                for (int d = 0; d < 8; ++d) {
                    float2 f = ubf2f(kp[d]);
                    sd += qv[2*d]*f.x + qv[2*d+1]*f.y;
                }
                sc[gg] = sd*0.25f + pb[hI*8 + gg];
                mx = fmaxf(mx, sc[gg]);
            }
            float ssum = 0.f;
            #pragma unroll
            for (int gg = 0; gg < 8; ++gg) { sc[gg] = __expf(sc[gg] - mx); ssum += sc[gg]; }
            float inv = 1.f / ssum;
            float ao[16];
            #pragma unroll
            for (int d = 0; d < 16; ++d) ao[d] = 0.f;
            #pragma unroll
            for (int gg = 0; gg < 8; ++gg) {
                float a = sc[gg]*inv;
                const uint32_t* vp = base + gg*24 + 16;
                #pragma unroll
                for (int d = 0; d < 8; ++d) {
                    float2 f = ubf2f(vp[d]);
                    ao[2*d]   += a*f.x;
                    ao[2*d+1] += a*f.y;
                }
            }
            #pragma unroll
            for (int d = 0; d < 8; ++d)
                aw[r*68 + hI*8 + d] = bf2(ao[2*d], ao[2*d+1]);
        }
    }

    // Phase C: token-dim dwconv on xc; read->regs, sync, write cols 0..63
    uint32_t cres[16];
    #pragma unroll
    for (int it = 0; it < 16; ++it) {
        int idx = tid + it*512;
        int r = idx >> 6, cw = idx & 63, n = r & 63;
        int c0 = cw*2;
        float2 m  = ubf2f(qw[r*260 + 192 + cw]);
        float2 lo = make_float2(0.f, 0.f), hi = make_float2(0.f, 0.f);
        if (n > 0)  lo = ubf2f(qw[(r-1)*260 + 192 + cw]);
        if (n < 63) hi = ubf2f(qw[(r+1)*260 + 192 + cw]);
        float d0 = lo.x*dw1_w[c0*3]   + m.x*dw1_w[c0*3+1] + hi.x*dw1_w[c0*3+2] + dw1_b[c0];
        float d1 = lo.y*dw1_w[c0*3+3] + m.y*dw1_w[c0*3+4] + hi.y*dw1_w[c0*3+5] + dw1_b[c0+1];
        cres[it] = bf2(d0, d1);
    }
    __syncthreads();
    stage_async(g_wbf + 4*16384, s_W, tid);   // out_w behind Phase C writes
    #pragma unroll
    for (int it = 0; it < 16; ++it) {
        int idx = tid + it*512;
        qw[(idx >> 6)*260 + (idx & 63)] = cres[it];
    }
    stage_wait0();
    __syncthreads();

    // Phase D: ao @ out_w^T + dconv @ tok_w^T -> g_att (bf16)
    float acc[2][4][4] = {};
    mma_gemm16(s_y, 136, s_W, acc, warp, lane);
    __syncthreads();
    stage_async(g_wbf + 5*16384, s_W, tid);
    stage_wait0();
    __syncthreads();
    mma_gemm16(s_qkv, 520, s_W, acc, warp, lane);
    uint32_t* ow = (uint32_t*)g_att + (size_t)win0*4096;
    #pragma unroll
    for (int mt = 0; mt < 2; ++mt)
        #pragma unroll
        for (int nt = 0; nt < 4; ++nt) {
            int r0 = rbase + mt*16;
            int c0 = cbase + nt*8 + 2*tg;
            float b0 = out_b[c0] + tok_b[c0], b1 = out_b[c0+1] + tok_b[c0+1];
            ow[ r0   *64 + (c0 >> 1)] = bf2(acc[mt][nt][0] + b0, acc[mt][nt][1] + b1);
            ow[(r0+8)*64 + (c0 >> 1)] = bf2(acc[mt][nt][2] + b0, acc[mt][nt][3] + b1);
        }
}

// ---------------- LN2 + lpw fused: register-resident, 2 CTAs/SM (no g_x1 write) ----------------
__global__ void __launch_bounds__(512, 2) k_ln2z(const float* __restrict__ x,
                                                 const float* __restrict__ w,
                                                 const float* __restrict__ b) {
    extern __shared__ __align__(16) char smem[];
    __nv_bfloat16* s_A = (__nv_bfloat16*)smem;            // 128*136
    __nv_bfloat16* s_W = (__nv_bfloat16*)(smem + 34816);  // 128*136
    int tid = threadIdx.x, bid = blockIdx.x;
    int warp = tid >> 5, lane = tid & 31;
    int w0 = (bid & 1) * 128;
    int h  = (bid >> 1) & 255;
    int bb = bid >> 9;
    stage_async(g_wbf + 6*16384, s_W, tid);

    int p = tid >> 2, q = tid & 3;
    int wc = w0 + p;
    const float* xp = x + (size_t)bb*CCH*65536 + h*256 + wc + (size_t)q*32*65536;
    float x1[32];
    #pragma unroll
    for (int i = 0; i < 32; ++i) x1[i] = xp[(size_t)i*65536];
    int win = (bb*32 + (h >> 3))*32 + (wc >> 3);
    int n   = (h & 7)*8 + (wc & 7);
    const uint4* ap = (const uint4*)((const uint32_t*)g_att + (size_t)win*4096 + n*64 + q*16);
    #pragma unroll
    for (int j4 = 0; j4 < 4; ++j4) {
        uint4 u = ap[j4];
        float2 f;
        f = ubf2f(u.x); x1[j4*8+0] += f.x; x1[j4*8+1] += f.y;
        f = ubf2f(u.y); x1[j4*8+2] += f.x; x1[j4*8+3] += f.y;
        f = ubf2f(u.z); x1[j4*8+4] += f.x; x1[j4*8+5] += f.y;
        f = ubf2f(u.w); x1[j4*8+6] += f.x; x1[j4*8+7] += f.y;
    }
    float sm = 0.f, sq = 0.f;
    #pragma unroll
    for (int i = 0; i < 32; ++i) { sm += x1[i]; sq += x1[i]*x1[i]; }
    sm += __shfl_xor_sync(0xffffffffu, sm, 1); sq += __shfl_xor_sync(0xffffffffu, sq, 1);
    sm += __shfl_xor_sync(0xffffffffu, sm, 2); sq += __shfl_xor_sync(0xffffffffu, sq, 2);
    float mu = sm * (1.f/128.f);
    float rs = rsqrtf(sq * (1.f/128.f) - mu*mu + 1e-5f);
    uint32_t* aw = (uint32_t*)s_A;
    #pragma unroll
    for (int j = 0; j < 16; ++j) {
        int c0 = q*32 + 2*j;
        float v0 = (x1[2*j]   - mu) * rs * w[c0]   + b[c0];
        float v1 = (x1[2*j+1] - mu) * rs * w[c0+1] + b[c0+1];
        aw[p*68 + q*16 + j] = bf2(v0, v1);
    }
    stage_wait0();
    __syncthreads();
    float acc[2][4][4] = {};
    mma_gemm16(s_A, 136, s_W, acc, warp, lane);
    int g = lane >> 2, tg = lane & 3;
    int rbase = (warp & 3) * 32 + g;
    int cbase = (warp >> 2) * 32;
    size_t pixb = (size_t)(bb*65536 + h*256 + w0);
    uint32_t* zw = (uint32_t*)g_z;
    #pragma unroll
    for (int mt = 0; mt < 2; ++mt)
        #pragma unroll
        for (int nt = 0; nt < 4; ++nt) {
            int r0 = rbase + mt*16;
            int c0 = cbase + nt*8 + 2*tg;
            zw[(pixb + r0)  *64 + (c0 >> 1)] = bf2(acc[mt][nt][0], acc[mt][nt][1]);
            zw[(pixb + r0+8)*64 + (c0 >> 1)] = bf2(acc[mt][nt][2], acc[mt][nt][3]);
        }
}

// ---------------- LeFF: residual reconstructed from g_att + x (no g_x1) ----------------
__global__ void __launch_bounds__(512, 2) k_leff(const float* __restrict__ x,
                                                 const float* __restrict__ ldw_w,
                                                 const float* __restrict__ ldw_b,
                                                 const float* __restrict__ fc1_b,
                                                 const float* __restrict__ fc2_b,
                                                 float* __restrict__ out) {
    extern __shared__ __align__(16) char smem[];
    __nv_bfloat16* s_d = (__nv_bfloat16*)smem;                   // 128*136
    __nv_bfloat16* s_t = (__nv_bfloat16*)(smem + 34816);         // 128*136
    __nv_bfloat16* s_W = (__nv_bfloat16*)(smem + 69632);         // 128*136
    float* s_f = (float*)(smem + 34816);                         // aliases s_t + s_W
    int tid = threadIdx.x, warp = tid >> 5, lane = tid & 31, bid = blockIdx.x;
    int w0 = (bid & 1) * 128;
    int h  = (bid >> 1) & 255;
    int bb = bid >> 9;

    stage_async(g_wbf + 7*16384, s_W, tid);    // fc1[0]

    // 3x3 depthwise over g_z (bf16 channels-last), uint4-vectorized (8 channels/thread)
    {
        const uint4* zw4 = (const uint4*)g_z;
        #pragma unroll
        for (int it = 0; it < 4; ++it) {
            int idx = tid + it*512;              // 2048 uint4
            int p = idx >> 4, c16 = idx & 15;
            int c0 = c16*8;
            int xx0 = w0 + p;
            float acc[8];
            #pragma unroll
            for (int j = 0; j < 8; ++j) acc[j] = ldw_b[c0 + j];
            #pragma unroll
            for (int dy = 0; dy < 3; ++dy) {
                int yy = h + dy - 1;
                if (yy < 0 || yy > 255) continue;
                #pragma unroll
                for (int dx = 0; dx < 3; ++dx) {
                    int xx = xx0 + dx - 1;
                    if (xx < 0 || xx > 255) continue;
                    uint4 u = zw4[((size_t)(bb*65536 + yy*256 + xx))*16 + c16];
                    float2 f;
                    f = ubf2f(u.x); acc[0] += f.x*ldw_w[(c0  )*9 + dy*3 + dx];
                                    acc[1] += f.y*ldw_w[(c0+1)*9 + dy*3 + dx];
                    f = ubf2f(u.y); acc[2] += f.x*ldw_w[(c0+2)*9 + dy*3 + dx];
                                    acc[3] += f.y*ldw_w[(c0+3)*9 + dy*3 + dx];
                    f = ubf2f(u.z); acc[4] += f.x*ldw_w[(c0+4)*9 + dy*3 + dx];
                                    acc[5] += f.y*ldw_w[(c0+5)*9 + dy*3 + dx];
                    f = ubf2f(u.w); acc[6] += f.x*ldw_w[(c0+6)*9 + dy*3 + dx];
                                    acc[7] += f.y*ldw_w[(c0+7)*9 + dy*3 + dx];
                }
            }
            uint4 o;
            o.x = bf2(acc[0], acc[1]); o.y = bf2(acc[2], acc[3]);
            o.z = bf2(acc[4], acc[5]); o.w = bf2(acc[6], acc[7]);
            *(uint4*)((uint32_t*)s_d + p*68 + c16*4) = o;
        }
    }

    int g = lane >> 2, tg = lane & 3;
    int rbase = (warp & 3) * 32 + g;
    int cbase = (warp >> 2) * 32;
    float oacc[2][4][4] = {};
    for (int jc = 0; jc < 4; ++jc) {
        stage_wait0();                       // fc1[jc] landed
        __syncthreads();
        uint32_t* tw = (uint32_t*)s_t;
        // half 0: MMA + gelu + store
        {
            float tacc[2][2][4] = {};
            mma_gemm16_n2(s_d, 136, s_W, tacc, warp, lane, 0);
            #pragma unroll
            for (int mt = 0; mt < 2; ++mt)
                #pragma unroll
                for (int nt = 0; nt < 2; ++nt) {
                    int r0 = rbase + mt*16;
                    int c0 = cbase + nt*8 + 2*tg;
                    float b0 = fc1_b[jc*128 + c0], b1 = fc1_b[jc*128 + c0 + 1];
                    float v0 = gelu_f(tacc[mt][nt][0] + b0);
                    float v1 = gelu_f(tacc[mt][nt][1] + b1);
                    float v2 = gelu_f(tacc[mt][nt][2] + b0);
                    float v3 = gelu_f(tacc[mt][nt][3] + b1);
                    tw[ r0   *68 + (c0 >> 1)] = bf2(v0, v1);
                    tw[(r0+8)*68 + (c0 >> 1)] = bf2(v2, v3);
                }
        }
        // half 1: MMA now; gelu AFTER issuing the fc2 stage so the load overlaps it
        {
            float tacc[2][2][4] = {};
            mma_gemm16_n2(s_d, 136, s_W, tacc, warp, lane, 1);
            __syncthreads();                             // all s_W reads retired
            stage_async(g_wbf + (11+jc)*16384, s_W, tid); // fc2[jc] flies under the gelu below
            #pragma unroll
            for (int mt = 0; mt < 2; ++mt)
                #pragma unroll
                for (int nt = 0; nt < 2; ++nt) {
                    int r0 = rbase + mt*16;
                    int c0 = cbase + 16 + nt*8 + 2*tg;
                    float b0 = fc1_b[jc*128 + c0], b1 = fc1_b[jc*128 + c0 + 1];
                    float v0 = gelu_f(tacc[mt][nt][0] + b0);
                    float v1 = gelu_f(tacc[mt][nt][1] + b1);
                    float v2 = gelu_f(tacc[mt][nt][2] + b0);
                    float v3 = gelu_f(tacc[mt][nt][3] + b1);
                    tw[ r0   *68 + (c0 >> 1)] = bf2(v0, v1);
                    tw[(r0+8)*68 + (c0 >> 1)] = bf2(v2, v3);
                }
        }
        stage_wait0();
        __syncthreads();                     // s_t complete + fc2 weights ready
        mma_gemm16(s_t, 136, s_W, oacc, warp, lane);
        __syncthreads();                     // fc2 weight + s_t reads done
        if (jc < 3) stage_async(g_wbf + (8+jc)*16384, s_W, tid);   // fc1[jc+1]
    }

    // epilogue: + fc2_b + att residual (bf16), stage fp32; x added at the coalesced write
    #pragma unroll
    for (int mt = 0; mt < 2; ++mt)
        #pragma unroll
        for (int nt = 0; nt < 4; ++nt) {
            int r0 = rbase + mt*16;
            int c0 = cbase + nt*8 + 2*tg;
            float b0 = fc2_b[c0], b1 = fc2_b[c0+1];
            #pragma unroll
            for (int rr = 0; rr < 2; ++rr) {
                int r = r0 + rr*8;
                int wc = w0 + r;
                int win = (bb*32 + (h >> 3))*32 + (wc >> 3);
                int n   = (h & 7)*8 + (wc & 7);
                float2 a = ubf2f(((const uint32_t*)g_att)[(size_t)win*4096 + n*64 + (c0 >> 1)]);
                s_f[r*129 + c0]     = oacc[mt][nt][2*rr]     + b0 + a.x;
                s_f[r*129 + c0 + 1] = oacc[mt][nt][2*rr + 1] + b1 + a.y;
            }
        }
    __syncthreads();
    for (int idx = tid; idx < 16384; idx += 512) {
        int c = idx >> 7, p = idx & 127;
        size_t gi = ((size_t)(bb*128 + c)*256 + h)*256 + w0 + p;
        out[gi] = s_f[p*129 + c] + x[gi];      // coalesced read of x fused into store
    }
}

// ---------------- launch ----------------
extern "C" void kernel_launch(void* const* d_in, const int* in_sizes, int n_in,
                              void* d_out, int out_size) {
    const float* x        = (const float*)d_in[0];
    const float* norm1_w  = (const float*)d_in[1];
    const float* norm1_b  = (const float*)d_in[2];
    const float* qkv_w    = (const float*)d_in[3];
    const float* qkv_b    = (const float*)d_in[4];
    const float* pos_bias = (const float*)d_in[5];
    const float* out_w    = (const float*)d_in[6];
    const float* out_b    = (const float*)d_in[7];
    const float* convp_w  = (const float*)d_in[8];
    const float* convp_b  = (const float*)d_in[9];
    const float* pw1_w    = (const float*)d_in[10];
    const float* pw1_b    = (const float*)d_in[11];
    const float* dw1_w    = (const float*)d_in[12];
    const float* dw1_b    = (const float*)d_in[13];
    const float* tok_w    = (const float*)d_in[14];
    const float* tok_b    = (const float*)d_in[15];
    const float* norm2_w  = (const float*)d_in[16];
    const float* norm2_b  = (const float*)d_in[17];
    const float* lpw_w    = (const float*)d_in[18];
    const float* ldw_w    = (const float*)d_in[19];
    const float* ldw_b    = (const float*)d_in[20];
    const float* fc1_w    = (const float*)d_in[21];
    const float* fc1_b    = (const float*)d_in[22];
    const float* fc2_w    = (const float*)d_in[23];
    const float* fc2_b    = (const float*)d_in[24];
    float* out = (float*)d_out;

    const int SM_REMSA = 133120 + 34816 + 34816;          // 202752
    const int SM_LN2Z  = 34816 + 34816;                   //  69632
    const int SM_LEFF  = 34816*3;                         // 104448
    cudaFuncSetAttribute(k_remsa, cudaFuncAttributeMaxDynamicSharedMemorySize, SM_REMSA);
    cudaFuncSetAttribute(k_ln2z,  cudaFuncAttributeMaxDynamicSharedMemorySize, SM_LN2Z);
    cudaFuncSetAttribute(k_leff,  cudaFuncAttributeMaxDynamicSharedMemorySize, SM_LEFF);

    k_prep <<<960,  256>>>(qkv_w, out_w, tok_w, lpw_w, fc1_w, fc2_w,
                           convp_w, convp_b, pw1_w, pw1_b);
    k_remsa<<<2048, 512, SM_REMSA>>>(x, norm1_w, norm1_b, qkv_b, pos_bias,
                                     out_b, tok_b, dw1_w, dw1_b);
    k_ln2z <<<2048, 512, SM_LN2Z>>>(x, norm2_w, norm2_b);
    k_leff <<<2048, 512, SM_LEFF>>>(x, ldw_w, ldw_b, fc1_b, fc2_b, out);
}